// round 6
// baseline (speedup 1.0000x reference)
#include <cuda_runtime.h>
#include <cuda_fp16.h>

#define B_  8
#define H_  8
#define QS_ 64
#define KS_ 512
#define A_  64
#define DH_ 64
#define KC_ 64
#define NC_ 8
#define QD_ 512
#define KD_ 512

typedef unsigned long long ull;

// scratch: per-chunk partial outputs + softmax stats
__device__ float g_pout[B_*H_*NC_*QS_*DH_];   // 8 MB
__device__ float g_Mx[B_*H_*NC_*QS_];
__device__ float g_Sx[B_*H_*NC_*QS_];

__device__ __forceinline__ float fast_tanh(float v) {
    float y; asm("tanh.approx.f32 %0, %1;" : "=f"(y) : "f"(v)); return y;
}
__device__ __forceinline__ ull pk2(float x, float y) {
    ull r; asm("mov.b64 %0, {%1, %2};" : "=l"(r) : "f"(x), "f"(y)); return r;
}
__device__ __forceinline__ float2 upk2(ull v) {
    float2 r; asm("mov.b64 {%0, %1}, %2;" : "=f"(r.x), "=f"(r.y) : "l"(v)); return r;
}
__device__ __forceinline__ ull ffma2(ull a, ull b, ull c) {
    ull d; asm("fma.rn.f32x2 %0, %1, %2, %3;" : "=l"(d) : "l"(a), "l"(b), "l"(c)); return d;
}

// ---------------- smem layout (bytes), total 53760 -> 4 CTAs/SM ----------------
//  s_xv   @0      f32[64][68] 17408   (query staging in ph1; x chunk (=K=V) after)
//  s_kph  @17408  half[64][72] 9216   ([a][k])
//  s_qph  @26624  half[64][72] 9216   ([a][q])
//  s_Wst  @35840  f32[64][68] 17408   (Wq, then Wk, then p f32[64][68])
//  s_bias @53248  f32[64]
//  s_w2   @53504  f32[64]
#define SMF_BYTES 53760

// 64 rows x 64 a projection GEMM: s_in[r*68+d], s_w[a*68+d] -> s_out[a*72+r] (half)
__device__ __forceinline__ void proj_gemm(
    const float* __restrict__ s_in, const float* __restrict__ s_w,
    __half* __restrict__ s_out, const float* __restrict__ s_bias,
    int tx, int ty)
{
    ull acc2[4][4];
#pragma unroll
    for (int i = 0; i < 4; i++)
#pragma unroll
        for (int j = 0; j < 4; j++) acc2[i][j] = 0ULL;

#pragma unroll
    for (int d4 = 0; d4 < 16; d4++) {
        ull wv[4][2];
#pragma unroll
        for (int j = 0; j < 4; j++) {
            float4 v = *(const float4*)&s_w[(tx + 16 * j) * 68 + d4 * 4];
            wv[j][0] = pk2(v.x, v.y); wv[j][1] = pk2(v.z, v.w);
        }
#pragma unroll
        for (int i = 0; i < 4; i++) {
            float4 v = *(const float4*)&s_in[(ty * 4 + i) * 68 + d4 * 4];
            ull r0 = pk2(v.x, v.y), r1 = pk2(v.z, v.w);
#pragma unroll
            for (int j = 0; j < 4; j++) {
                acc2[i][j] = ffma2(r0, wv[j][0], acc2[i][j]);
                acc2[i][j] = ffma2(r1, wv[j][1], acc2[i][j]);
            }
        }
    }
#pragma unroll
    for (int i = 0; i < 4; i++)
#pragma unroll
        for (int j = 0; j < 4; j++) {
            float2 p = upk2(acc2[i][j]);
            float v = p.x + p.y + (s_bias ? s_bias[tx + 16 * j] : 0.f);
            s_out[(tx + 16 * j) * 72 + ty * 4 + i] = __float2half_rn(v);
        }
}

__global__ void __launch_bounds__(256, 4) fused_kernel(
    const float* __restrict__ x, const float* __restrict__ query,
    const float* __restrict__ W, const float* __restrict__ bias,
    const float* __restrict__ w2, const unsigned char* __restrict__ mask)
{
    extern __shared__ char sm[];
    float*  s_xv  = (float*)(sm);
    __half* s_kph = (__half*)(sm + 17408);
    __half* s_qph = (__half*)(sm + 26624);
    float*  s_Wst = (float*)(sm + 35840);
    float*  s_p   = (float*)(sm + 35840);
    float*  s_bias= (float*)(sm + 53248);
    float*  s_w2  = (float*)(sm + 53504);

    const int kc = blockIdx.x, h = blockIdx.y, b = blockIdx.z;
    const int tid = threadIdx.x;
    const int tx = tid & 15, ty = tid >> 4;
    const int bh = b * H_ + h;
    const float NEG_INF = __int_as_float(0xff800000);

    if (tid < 64) { s_bias[tid] = bias[tid]; s_w2[tid] = w2[tid]; }

    // ---- phase 1: stage query [64][68-stride] + Wq ----
#pragma unroll
    for (int i = 0; i < 4; i++) {
        int idx = tid + 256 * i; int q = idx >> 4, d4 = idx & 15;
        *(float4*)&s_xv[q * 68 + d4 * 4] =
            *(const float4*)&query[(size_t)(b * QS_ + q) * QD_ + h * DH_ + d4 * 4];
    }
#pragma unroll
    for (int i = 0; i < 4; i++) {
        int idx = tid + 256 * i; int a = idx >> 4, d4 = idx & 15;
        *(float4*)&s_Wst[a * 68 + d4 * 4] = *(const float4*)&W[a * 128 + 64 + d4 * 4];
    }
    __syncthreads();

    // ---- qp projection -> s_qph[a][q] ----
    proj_gemm(s_xv, s_Wst, s_qph, s_bias, tx, ty);
    __syncthreads();

    // ---- phase 2: stage x chunk [64][68-stride] + Wk ----
#pragma unroll
    for (int i = 0; i < 4; i++) {
        int idx = tid + 256 * i; int k = idx >> 4, d4 = idx & 15;
        *(float4*)&s_xv[k * 68 + d4 * 4] =
            *(const float4*)&x[((size_t)b * KS_ + kc * KC_ + k) * KD_ + h * DH_ + d4 * 4];
    }
#pragma unroll
    for (int i = 0; i < 4; i++) {
        int idx = tid + 256 * i; int a = idx >> 4, d4 = idx & 15;
        *(float4*)&s_Wst[a * 68 + d4 * 4] = *(const float4*)&W[a * 128 + d4 * 4];
    }
    __syncthreads();

    // ---- kp projection -> s_kph[a][k] ----
    proj_gemm(s_xv, s_Wst, s_kph, (const float*)0, tx, ty);
    __syncthreads();

    // ---- phase 3: scores[q][k] = sum_a w2[a]*tanh(qp[q][a] + kp[k][a]) ----
    const int q0 = ty * 4, k0 = tx * 4;
    float acc[4][4];
#pragma unroll
    for (int j = 0; j < 4; j++)
#pragma unroll
        for (int i = 0; i < 4; i++) acc[j][i] = 0.f;

#pragma unroll 4
    for (int a = 0; a < A_; a++) {
        uint2 qr = *(const uint2*)&s_qph[a * 72 + q0];
        uint2 kr = *(const uint2*)&s_kph[a * 72 + k0];
        float2 qf0 = __half22float2(((const __half2*)&qr)[0]);
        float2 qf1 = __half22float2(((const __half2*)&qr)[1]);
        float2 kf0 = __half22float2(((const __half2*)&kr)[0]);
        float2 kf1 = __half22float2(((const __half2*)&kr)[1]);
        float w2a = s_w2[a];
        float qs[4] = {qf0.x, qf0.y, qf1.x, qf1.y};
        float ks[4] = {kf0.x, kf0.y, kf1.x, kf1.y};
#pragma unroll
        for (int j = 0; j < 4; j++)
#pragma unroll
            for (int i = 0; i < 4; i++)
                acc[j][i] += w2a * fast_tanh(qs[j] + ks[i]);
    }

    // ---- phase 4: chunk-local softmax stats (shuffles over the 16-lane k-group) ----
    {
        uchar4 mk4 = *(const uchar4*)&mask[b * KS_ + kc * KC_ + k0];
        unsigned char mk[4] = {mk4.x, mk4.y, mk4.z, mk4.w};
#pragma unroll
        for (int i = 0; i < 4; i++)
            if (mk[i]) {
#pragma unroll
                for (int j = 0; j < 4; j++) acc[j][i] = NEG_INF;
            }

        float rowmax[4], rowsum[4];
#pragma unroll
        for (int j = 0; j < 4; j++) {
            float mx = NEG_INF;
#pragma unroll
            for (int i = 0; i < 4; i++) mx = fmaxf(mx, acc[j][i]);
#pragma unroll
            for (int o = 8; o; o >>= 1) mx = fmaxf(mx, __shfl_xor_sync(0xffffffffu, mx, o));
            float s = 0.f;
#pragma unroll
            for (int i = 0; i < 4; i++) {
                float p = mk[i] ? 0.f : __expf(acc[j][i] - mx);
                acc[j][i] = p;
                s += p;
            }
#pragma unroll
            for (int o = 8; o; o >>= 1) s += __shfl_xor_sync(0xffffffffu, s, o);
            rowmax[j] = mx; rowsum[j] = s;
        }
        if (tx == 0) {
#pragma unroll
            for (int j = 0; j < 4; j++) {
                g_Mx[(bh * NC_ + kc) * QS_ + q0 + j] = rowmax[j];
                g_Sx[(bh * NC_ + kc) * QS_ + q0 + j] = rowsum[j];
            }
        }
        // write unnormalized p over the (dead) weight-staging region
#pragma unroll
        for (int j = 0; j < 4; j++)
            *(float4*)&s_p[(q0 + j) * 68 + k0] =
                make_float4(acc[j][0], acc[j][1], acc[j][2], acc[j][3]);
    }
    __syncthreads();

    // ---- phase 5: partial out = p @ V  (4q x 4d per thread) ----
    {
        const int txd = tid & 15, tyq = tid >> 4;
        const int d0 = txd * 4, q0b = tyq * 4;
        ull o2[4][2];
#pragma unroll
        for (int j = 0; j < 4; j++) { o2[j][0] = 0ULL; o2[j][1] = 0ULL; }

#pragma unroll 4
        for (int k = 0; k < KC_; k++) {
            float4 v = *(float4*)&s_xv[k * 68 + d0];
            ull v0 = pk2(v.x, v.y), v1 = pk2(v.z, v.w);
#pragma unroll
            for (int j = 0; j < 4; j++) {
                float p = s_p[(q0b + j) * 68 + k];
                ull p2 = pk2(p, p);
                o2[j][0] = ffma2(p2, v0, o2[j][0]);
                o2[j][1] = ffma2(p2, v1, o2[j][1]);
            }
        }
#pragma unroll
        for (int j = 0; j < 4; j++) {
            float2 a0 = upk2(o2[j][0]), a1 = upk2(o2[j][1]);
            *(float4*)&g_pout[(size_t)((bh * NC_ + kc) * QS_ + q0b + j) * DH_ + d0] =
                make_float4(a0.x, a0.y, a1.x, a1.y);
        }
    }
}

// ---------------- combine: merge 8 chunk partials per (b,h) ----------------
// grid (4, B*H), block 256: one float4 output per thread.
__global__ void __launch_bounds__(256) combine_kernel(float* __restrict__ out)
{
    const int idx = blockIdx.x * 256 + threadIdx.x;   // 0..1023 per bh
    const int bh = blockIdx.y;
    const int b = bh >> 3, h = bh & 7;
    const int q = idx >> 4, dg = idx & 15, d0 = dg * 4;
    const float NEG_INF = __int_as_float(0xff800000);

    float Mc[NC_], Sc[NC_];
    float M = NEG_INF;
#pragma unroll
    for (int c = 0; c < NC_; c++) {
        Mc[c] = g_Mx[(bh * NC_ + c) * QS_ + q];
        Sc[c] = g_Sx[(bh * NC_ + c) * QS_ + q];
        M = fmaxf(M, Mc[c]);
    }
    float w[NC_], denom = 0.f;
#pragma unroll
    for (int c = 0; c < NC_; c++) {
        w[c] = __expf(Mc[c] - M);
        denom += w[c] * Sc[c];
    }
    float inv = 1.f / denom;

    float4 a0 = make_float4(0.f, 0.f, 0.f, 0.f);
#pragma unroll
    for (int c = 0; c < NC_; c++) {
        float4 v = *(const float4*)&g_pout[(size_t)((bh * NC_ + c) * QS_ + q) * DH_ + d0];
        a0.x += w[c] * v.x; a0.y += w[c] * v.y;
        a0.z += w[c] * v.z; a0.w += w[c] * v.w;
    }
    a0.x *= inv; a0.y *= inv; a0.z *= inv; a0.w *= inv;

    *(float4*)&out[(size_t)(b * QS_ + q) * QD_ + h * DH_ + d0] = a0;
}

// ---------------- launch ----------------
extern "C" void kernel_launch(void* const* d_in, const int* in_sizes, int n_in,
                              void* d_out, int out_size) {
    const float* x     = (const float*)d_in[0];
    const float* query = (const float*)d_in[1];
    const float* W     = (const float*)d_in[2];
    const float* bias  = (const float*)d_in[3];
    const float* w2    = (const float*)d_in[4];
    const unsigned char* mask = (const unsigned char*)d_in[5];
    float* out = (float*)d_out;

    cudaFuncSetAttribute(fused_kernel, cudaFuncAttributeMaxDynamicSharedMemorySize, SMF_BYTES);

    fused_kernel<<<dim3(NC_, H_, B_), 256, SMF_BYTES>>>(x, query, W, bias, w2, mask);
    combine_kernel<<<dim3(4, B_ * H_), 256>>>(out);
}